// round 14
// baseline (speedup 1.0000x reference)
#include <cuda_runtime.h>
#include <cuda_fp16.h>
#include <math.h>
#include <stdint.h>

#define BB 8
#define TT 2048
#define DIMX 512
#define DMX 128
#define DINNERX 256
#define NSTATEX 16
#define HDIMX 64
#define NHX 4
#define CONVD 288
#define PROJD 548
#define PROJPAD 576
#define LNUM 2
#define BT (BB*TT)          // 16384
#define QC 128
#define NCHK (TT/QC)        // 16
#define BHX (BB*NHX)        // 32
#define EPSF 1e-5f

// ------------------------- scratch (static device memory) -------------------
__device__ float g_H[BT*DMX];
__device__ float g_PROJ[BT*PROJD];
__device__ __half g_CONVX[BT*CONVD];
__device__ float g_DT[BHX*TT];
__device__ float g_CUM[BHX*TT];
__device__ float g_SLOC[BHX*NCHK*HDIMX*NSTATEX];
__device__ __half g_Y[BT*DINNERX];
__device__ float g_POOLP[BB*32*DMX];

__device__ __half g_xh[BT*DIMX];
__device__ __half g_hnh[BT*DMX];
__device__ __half g_ynh[BT*DINNERX];
__device__ __half g_w1h[DMX*DIMX];                 // in_w^T [128][512]
__device__ __half g_w2h[LNUM*PROJPAD*DMX];         // inproj^T [576][128]
__device__ __half g_w3h[LNUM*DMX*DINNERX];         // outproj^T [128][256]

// ------------------------------ PTX helpers ---------------------------------
__device__ __forceinline__ uint32_t smem_u32(const void* p) {
    uint32_t a;
    asm("{ .reg .u64 t; cvta.to.shared.u64 t, %1; cvt.u32.u64 %0, t; }" : "=r"(a) : "l"(p));
    return a;
}
__device__ __forceinline__ void ldsm_x4(uint32_t* r, uint32_t addr) {
    asm volatile("ldmatrix.sync.aligned.m8n8.x4.shared.b16 {%0,%1,%2,%3}, [%4];"
        : "=r"(r[0]), "=r"(r[1]), "=r"(r[2]), "=r"(r[3]) : "r"(addr));
}
__device__ __forceinline__ void mma16816(float* c, const uint32_t* a, const uint32_t* b) {
    asm volatile("mma.sync.aligned.m16n8k16.row.col.f32.f16.f16.f32 "
        "{%0,%1,%2,%3}, {%4,%5,%6,%7}, {%8,%9}, {%0,%1,%2,%3};"
        : "+f"(c[0]), "+f"(c[1]), "+f"(c[2]), "+f"(c[3])
        : "r"(a[0]), "r"(a[1]), "r"(a[2]), "r"(a[3]), "r"(b[0]), "r"(b[1]));
}
__device__ __forceinline__ void cp16(uint32_t saddr, const void* g) {
    asm volatile("cp.async.ca.shared.global [%0], [%1], 16;" :: "r"(saddr), "l"(g));
}
__device__ __forceinline__ void cp_commit() {
    asm volatile("cp.async.commit_group;" ::: "memory");
}
template<int N> __device__ __forceinline__ void cp_wait() {
    asm volatile("cp.async.wait_group %0;" :: "n"(N) : "memory");
}

#define LDSA 72

// ------------------------------ proj GEMM (128x64 tile) ----------------------
#define A_BYTES (128*LDSA*2)                 // 18432
#define B_BYTES (64*LDSA*2)                  // 9216
#define OFF_B A_BYTES
#define STAGE_BYTES (A_BYTES + B_BYTES)      // 27648
#define SM_TOTAL (2*STAGE_BYTES)             // 55296

__global__ __launch_bounds__(256, 2) void mma_gemm_proj(
    const __half* __restrict__ A, const __half* __restrict__ Wt,
    float* __restrict__ C, int N, int K)
{
    extern __shared__ char smem[];
    uint32_t sb = smem_u32(smem);
    int tid = threadIdx.x, wid = tid >> 5, lane = tid & 31;
    int m0 = blockIdx.y * 128, n0 = blockIdx.x * 64;
    int wm = (wid & 3) * 32, wn = (wid >> 2) * 32;

    float acc[2][4][4];
#pragma unroll
    for (int i = 0; i < 2; i++)
#pragma unroll
        for (int j = 0; j < 4; j++)
#pragma unroll
            for (int q = 0; q < 4; q++) acc[i][j][q] = 0.f;

    int lr = lane & 15;
    uint32_t aOff[2];
#pragma unroll
    for (int mt = 0; mt < 2; mt++)
        aOff[mt] = (uint32_t)((wm + mt * 16 + lr) * (LDSA * 2) + (lane >> 4) * 16);
    uint32_t bOff[2];
    {
        int q = lane >> 3, rr = lane & 7;
#pragma unroll
        for (int p = 0; p < 2; p++) {
            int row = wn + p * 16 + (q >> 1) * 8 + rr;
            bOff[p] = (uint32_t)(OFF_B + row * (LDSA * 2) + (q & 1) * 16);
        }
    }

    int nstage = K >> 6;
    auto load_stage = [&](int buf, int k0) {
        uint32_t base = sb + buf * STAGE_BYTES;
#pragma unroll
        for (int i = 0; i < 4; i++) {
            int li = tid + i * 256;
            int r = li >> 3, g8 = li & 7;
            uint32_t so = (uint32_t)(r * (LDSA * 2) + g8 * 16);
            cp16(base + so, A + (size_t)(m0 + r) * K + k0 + g8 * 8);
        }
#pragma unroll
        for (int i = 0; i < 2; i++) {
            int li = tid + i * 256;
            int r = li >> 3, g8 = li & 7;
            uint32_t so = (uint32_t)(r * (LDSA * 2) + g8 * 16);
            cp16(base + OFF_B + so, Wt + (size_t)(n0 + r) * K + k0 + g8 * 8);
        }
    };

    load_stage(0, 0);
    cp_commit();

    for (int s = 0; s < nstage; s++) {
        if (s + 1 < nstage) load_stage((s + 1) & 1, (s + 1) * 64);
        cp_commit();
        if (s + 1 < nstage) cp_wait<1>(); else cp_wait<0>();
        __syncthreads();

        uint32_t sbuf = sb + (s & 1) * STAGE_BYTES;
#pragma unroll
        for (int ks = 0; ks < 64; ks += 16) {
            uint32_t kb = (uint32_t)(ks * 2);
            uint32_t ah[2][4], b4[2][4];
#pragma unroll
            for (int mt = 0; mt < 2; mt++)
                ldsm_x4(ah[mt], sbuf + aOff[mt] + kb);
#pragma unroll
            for (int p = 0; p < 2; p++)
                ldsm_x4(b4[p], sbuf + bOff[p] + kb);
#pragma unroll
            for (int mt = 0; mt < 2; mt++)
#pragma unroll
                for (int p = 0; p < 2; p++)
#pragma unroll
                    for (int u = 0; u < 2; u++)
                        mma16816(acc[mt][2 * p + u], ah[mt], &b4[p][u * 2]);
        }
        __syncthreads();
    }

    float* S = (float*)smem;          // [128][68]
    const int SW = 68;
    int crow = lane >> 2, ccol = (lane & 3) * 2;
#pragma unroll
    for (int mt = 0; mt < 2; mt++)
#pragma unroll
        for (int nt = 0; nt < 4; nt++) {
            int r = wm + mt * 16 + crow;
            int cc = wn + nt * 8 + ccol;
            S[r * SW + cc]           = acc[mt][nt][0];
            S[r * SW + cc + 1]       = acc[mt][nt][1];
            S[(r + 8) * SW + cc]     = acc[mt][nt][2];
            S[(r + 8) * SW + cc + 1] = acc[mt][nt][3];
        }
    __syncthreads();
#pragma unroll
    for (int it = 0; it < 32; it++) {
        int li = tid + it * 256;
        int cc = li & 63, r = li >> 6;
        int col = n0 + cc;
        if (col < N) C[(size_t)(m0 + r) * N + col] = S[r * SW + cc];
    }
}

// ================= DM-output GEMM (64x128 tile) + fused rmsnorm ==============
// C rows complete per block -> epilogue does +bias / +=H, writes H, and
// (optionally) row-rmsnorm -> fp16 HN for the next consumer.
#define A2_BYTES (64*LDSA*2)                 // 9216
#define B2_BYTES (128*LDSA*2)                // 18432
#define OFF_B2 A2_BYTES
// stage = 27648 (same as proj), 2 buffers = 55296

template<int MODE, bool NORM>   // MODE 0: H=D+bias ; 2: H+=D
__global__ __launch_bounds__(256, 2) void mma_gemm_dm(
    const __half* __restrict__ A, const __half* __restrict__ Wt,
    const float* __restrict__ bias, const float* __restrict__ nw,
    float* __restrict__ H, __half* __restrict__ HN, int K)
{
    extern __shared__ char smem[];
    uint32_t sb = smem_u32(smem);
    int tid = threadIdx.x, wid = tid >> 5, lane = tid & 31;
    int m0 = blockIdx.x * 64;
    int wm = (wid & 3) * 16, wn = (wid >> 2) * 64;

    float acc[8][4];
#pragma unroll
    for (int j = 0; j < 8; j++)
#pragma unroll
        for (int q = 0; q < 4; q++) acc[j][q] = 0.f;

    int lr = lane & 15;
    uint32_t aOff = (uint32_t)((wm + lr) * (LDSA * 2) + (lane >> 4) * 16);
    uint32_t bOff[4];
    {
        int q = lane >> 3, rr = lane & 7;
#pragma unroll
        for (int p = 0; p < 4; p++) {
            int row = wn + p * 16 + (q >> 1) * 8 + rr;
            bOff[p] = (uint32_t)(OFF_B2 + row * (LDSA * 2) + (q & 1) * 16);
        }
    }

    int nstage = K >> 6;
    auto load_stage = [&](int buf, int k0) {
        uint32_t base = sb + buf * STAGE_BYTES;
#pragma unroll
        for (int i = 0; i < 2; i++) {
            int li = tid + i * 256;              // 512 chunks for A (64 rows)
            int r = li >> 3, g8 = li & 7;
            uint32_t so = (uint32_t)(r * (LDSA * 2) + g8 * 16);
            cp16(base + so, A + (size_t)(m0 + r) * K + k0 + g8 * 8);
        }
#pragma unroll
        for (int i = 0; i < 4; i++) {
            int li = tid + i * 256;              // 1024 chunks for B (128 rows)
            int r = li >> 3, g8 = li & 7;
            uint32_t so = (uint32_t)(r * (LDSA * 2) + g8 * 16);
            cp16(base + OFF_B2 + so, Wt + (size_t)r * K + k0 + g8 * 8);
        }
    };

    load_stage(0, 0);
    cp_commit();

    for (int s = 0; s < nstage; s++) {
        if (s + 1 < nstage) load_stage((s + 1) & 1, (s + 1) * 64);
        cp_commit();
        if (s + 1 < nstage) cp_wait<1>(); else cp_wait<0>();
        __syncthreads();

        uint32_t sbuf = sb + (s & 1) * STAGE_BYTES;
#pragma unroll
        for (int ks = 0; ks < 64; ks += 16) {
            uint32_t kb = (uint32_t)(ks * 2);
            uint32_t ah[4], b4[4][4];
            ldsm_x4(ah, sbuf + aOff + kb);
#pragma unroll
            for (int p = 0; p < 4; p++)
                ldsm_x4(b4[p], sbuf + bOff[p] + kb);
#pragma unroll
            for (int p = 0; p < 4; p++)
#pragma unroll
                for (int u = 0; u < 2; u++)
                    mma16816(acc[2 * p + u], ah, &b4[p][u * 2]);
        }
        __syncthreads();
    }

    // ---------------- epilogue with fused rmsnorm ----------------
    float* S = (float*)smem;          // [64][132] = 33792 B
    const int SW = 132;
    int crow = lane >> 2, ccol = (lane & 3) * 2;
#pragma unroll
    for (int nt = 0; nt < 8; nt++) {
        int r = wm + crow;
        int cc = wn + nt * 8 + ccol;
        S[r * SW + cc]           = acc[nt][0];
        S[r * SW + cc + 1]       = acc[nt][1];
        S[(r + 8) * SW + cc]     = acc[nt][2];
        S[(r + 8) * SW + cc + 1] = acc[nt][3];
    }
    __syncthreads();

    int r = tid >> 2, q = tid & 3;     // 64 rows x 4 lanes
    float* Sr = S + r * SW + q * 32;
    size_t hbase = (size_t)(m0 + r) * DMX + q * 32;
    float ss = 0.f;
#pragma unroll
    for (int k = 0; k < 32; k++) {
        float v = Sr[k];
        if (MODE == 0) v += bias[q * 32 + k];
        if (MODE == 2) v += H[hbase + k];
        H[hbase + k] = v;
        Sr[k] = v;
        ss += v * v;
    }
    if (NORM) {
        ss += __shfl_xor_sync(0xffffffffu, ss, 1);
        ss += __shfl_xor_sync(0xffffffffu, ss, 2);
        float rv = rsqrtf(ss * (1.f / DMX) + EPSF);
#pragma unroll
        for (int k = 0; k < 32; k += 2) {
            float w0 = nw[q * 32 + k], w1 = nw[q * 32 + k + 1];
            __half2 h2 = __floats2half2_rn(Sr[k] * rv * w0, Sr[k + 1] * rv * w1);
            *(__half2*)(HN + hbase + k) = h2;
        }
    }
}

// --------------------------- fused prep (x split + weight transposes) --------
#define XN4 (BT*DIMX/4)
#define TS_R1 (DMX*DIMX)
#define TS_R2 (LNUM*PROJPAD*DMX)
#define TS_R3 (LNUM*DMX*DINNERX)
#define PREP_N (XN4 + TS_R1 + TS_R2 + TS_R3)
__global__ void prep_kernel(const float* __restrict__ x,
                            const float* __restrict__ in_w,
                            const float* __restrict__ inproj_w,
                            const float* __restrict__ outproj_w)
{
    int idx = blockIdx.x * blockDim.x + threadIdx.x;
    if (idx < XN4) {
        float4 v = ((const float4*)x)[idx];
        __half h[4] = { __float2half_rn(v.x), __float2half_rn(v.y),
                        __float2half_rn(v.z), __float2half_rn(v.w) };
        *(uint2*)(g_xh + (size_t)idx * 4) = *(uint2*)h;
        return;
    }
    idx -= XN4;
    if (idx < TS_R1) {
        int n = idx / DIMX, k = idx % DIMX;
        g_w1h[idx] = __float2half_rn(in_w[(size_t)k * DMX + n]);
        return;
    }
    idx -= TS_R1;
    if (idx < TS_R2) {
        int l = idx / (PROJPAD * DMX), r = idx % (PROJPAD * DMX);
        int n = r / DMX, k = r % DMX;
        float v = (n < PROJD) ? inproj_w[(size_t)l * DMX * PROJD + (size_t)k * PROJD + n] : 0.f;
        g_w2h[idx] = __float2half_rn(v);
        return;
    }
    idx -= TS_R2;
    if (idx < TS_R3) {
        int l = idx / (DMX * DINNERX), r = idx % (DMX * DINNERX);
        int n = r / DINNERX, k = r % DINNERX;
        g_w3h[idx] = __float2half_rn(outproj_w[(size_t)l * DINNERX * DMX + (size_t)k * DMX + n]);
    }
}

// ------------------------ causal conv + silu (fp16 out) ----------------------
__global__ __launch_bounds__(288) void conv_kernel(const float* __restrict__ cw,
                                                   const float* __restrict__ cb)
{
    int b = blockIdx.y;
    int t0 = blockIdx.x * 64;
    int c = threadIdx.x;
    float w0 = cw[c*4], w1 = cw[c*4+1], w2 = cw[c*4+2], w3 = cw[c*4+3];
    float bias = cb[c];
    size_t base = (size_t)(b * TT) * PROJD + DINNERX + c;
    float xm3 = 0.f, xm2 = 0.f, xm1 = 0.f;
    if (t0 >= 3) {
        xm3 = g_PROJ[base + (size_t)(t0-3) * PROJD];
        xm2 = g_PROJ[base + (size_t)(t0-2) * PROJD];
        xm1 = g_PROJ[base + (size_t)(t0-1) * PROJD];
    }
    for (int i = 0; i < 8; i++) {
        float xv[8];
#pragma unroll
        for (int j = 0; j < 8; j++)
            xv[j] = g_PROJ[base + (size_t)(t0 + i*8 + j) * PROJD];
#pragma unroll
        for (int j = 0; j < 8; j++) {
            float a = bias + w0*xm3 + w1*xm2 + w2*xm1 + w3*xv[j];
            g_CONVX[(size_t)(b * TT + t0 + i*8 + j) * CONVD + c] =
                __float2half_rn(a / (1.f + __expf(-a)));
            xm3 = xm2; xm2 = xm1; xm1 = xv[j];
        }
    }
}

// ---------------- chunkstate (fused softplus + cumsum + local state) ---------
__global__ __launch_bounds__(256) void chunkstate_kernel(const float* __restrict__ Alog,
                                                         const float* __restrict__ dtb)
{
    int c = blockIdx.x, bh = blockIdx.y;
    int b = bh >> 2, h = bh & 3;
    int tid = threadIdx.x;
    __shared__ float sc[QC];
    __shared__ float sdt[QC];
    __shared__ float coef[QC];
    __shared__ float Xs[16][HDIMX];
    __shared__ float Bsh[16][NSTATEX];
    int cbase = bh * TT + c * QC;
    size_t rowbase = (size_t)(b * TT + c * QC);

    float Ah = -__expf(Alog[h]);
    if (tid < QC) {
        float v = g_PROJ[(size_t)(b * TT + c * QC + tid) * PROJD + DINNERX + CONVD + h] + dtb[h];
        float sp = (v > 20.f) ? v : log1pf(__expf(v));
        sdt[tid] = sp;
        sc[tid] = sp * Ah;
    }
    __syncthreads();
#pragma unroll
    for (int off = 1; off < QC; off <<= 1) {
        float x = 0.f;
        if (tid < QC && tid >= off) x = sc[tid - off];
        __syncthreads();
        if (tid < QC) sc[tid] += x;
        __syncthreads();
    }
    if (tid < QC) {
        g_DT[cbase + tid]  = sdt[tid];
        g_CUM[cbase + tid] = sc[tid];
        coef[tid] = __expf(sc[QC - 1] - sc[tid]) * sdt[tid];
    }

    float acc[4] = {0.f, 0.f, 0.f, 0.f};
    int p = tid >> 2, ng = (tid & 3) * 4;
    for (int tt = 0; tt < QC; tt += 16) {
        __syncthreads();
#pragma unroll
        for (int j = 0; j < 4; j++) {
            int li = tid + j * 256;
            int r = li >> 6, pp = li & 63;
            Xs[r][pp] = __half2float(g_CONVX[(rowbase + tt + r) * CONVD + h * 64 + pp]);
        }
        {
            int r = tid >> 4, n = tid & 15;
            Bsh[r][n] = __half2float(g_CONVX[(rowbase + tt + r) * CONVD + 256 + n]);
        }
        __syncthreads();
#pragma unroll
        for (int r = 0; r < 16; r++) {
            float cx = coef[tt + r] * Xs[r][p];
#pragma unroll
            for (int j = 0; j < 4; j++) acc[j] += cx * Bsh[r][ng + j];
        }
    }
    size_t dst = ((size_t)bh * NCHK + c) * (HDIMX * NSTATEX) + p * NSTATEX + ng;
    *(float4*)(g_SLOC + dst) = make_float4(acc[0], acc[1], acc[2], acc[3]);
}

// ============================ SSD via HMMA ===================================
#define SCB_STR 24
#define XT_STR 152
#define OFF_SC 0
#define OFF_SB 6144
#define OFF_XT 12288
#define OFF_G  31744
#define OFF_CUM 70656
#define OFF_SDT 71168
#define SSD_SMEM 71680

__global__ __launch_bounds__(256, 2) void ssd_mma_kernel(const float* __restrict__ Dp)
{
    extern __shared__ char sm[];
    __half* sC  = (__half*)(sm + OFF_SC);
    __half* sB  = (__half*)(sm + OFF_SB);
    __half* sXT = (__half*)(sm + OFF_XT);
    __half* sG  = (__half*)(sm + OFF_G);
    float*  sCum = (float*)(sm + OFF_CUM);
    float*  sDt  = (float*)(sm + OFF_SDT);
    float*  sYf  = (float*)(sm + OFF_G);
    uint32_t sb = smem_u32(sm);

    int c = blockIdx.x, bh = blockIdx.y;
    int b = bh >> 2, h = bh & 3;
    int tid = threadIdx.x, wid = tid >> 5, lane = tid & 31;
    size_t rowbase = (size_t)(b * TT + c * QC);
    int cbase = bh * TT + c * QC;

    if (tid < QC) { sCum[tid] = g_CUM[cbase + tid]; sDt[tid] = g_DT[cbase + tid]; }
#pragma unroll
    for (int jj = 0; jj < 8; jj++) {
        int e = tid + jj * 256;
        int r = e >> 4, n = e & 15;
        sC[r * SCB_STR + n] = g_CONVX[(rowbase + r) * CONVD + 272 + n];
        sB[r * SCB_STR + n] = g_CONVX[(rowbase + r) * CONVD + 256 + n];
    }
#pragma unroll
    for (int jj = 0; jj < 32; jj++) {
        int e = tid + jj * 256;
        int s = e >> 6, p = e & 63;
        sXT[p * XT_STR + s] = g_CONVX[(rowbase + s) * CONVD + h * 64 + p];
    }
    {
        size_t sbase = (size_t)bh * NCHK * (HDIMX * NSTATEX);
        int i = tid * 4;
        float4 s4 = make_float4(0.f, 0.f, 0.f, 0.f);
        for (int j = 0; j < c; j++) {
            float dj = __expf(g_CUM[bh * TT + j * QC + QC - 1]);
            float4 a = *(const float4*)(g_SLOC + sbase + j * (HDIMX * NSTATEX) + i);
            s4.x = s4.x * dj + a.x; s4.y = s4.y * dj + a.y;
            s4.z = s4.z * dj + a.z; s4.w = s4.w * dj + a.w;
        }
        int p = i >> 4, n0 = i & 15;
        __half hv[4] = { __float2half_rn(s4.x), __float2half_rn(s4.y),
                         __float2half_rn(s4.z), __float2half_rn(s4.w) };
        *(uint2*)(sXT + p * XT_STR + 128 + n0) = *(uint2*)hv;
    }
    __syncthreads();

    // phase A: S = C @ B^T
    int wm = (wid & 3) * 32, wn = (wid >> 2) * 64;
    float sacc[2][8][4];
#pragma unroll
    for (int i = 0; i < 2; i++)
#pragma unroll
        for (int j = 0; j < 8; j++)
#pragma unroll
            for (int q = 0; q < 4; q++) sacc[i][j][q] = 0.f;
    {
        uint32_t aC[2][4], bB[4][4];
        int lr = lane & 15;
#pragma unroll
        for (int mt = 0; mt < 2; mt++)
            ldsm_x4(aC[mt], sb + OFF_SC + (uint32_t)((wm + mt * 16 + lr) * (SCB_STR * 2) + (lane >> 4) * 16));
        int q = lane >> 3, rr = lane & 7;
#pragma unroll
        for (int p4 = 0; p4 < 4; p4++) {
            int row = wn + p4 * 16 + (q >> 1) * 8 + rr;
            ldsm_x4(bB[p4], sb + OFF_SB + (uint32_t)(row * (SCB_STR * 2) + (q & 1) * 16));
        }
#pragma unroll
        for (int mt = 0; mt < 2; mt++)
#pragma unroll
            for (int p4 = 0; p4 < 4; p4++)
#pragma unroll
                for (int u = 0; u < 2; u++)
                    mma16816(sacc[mt][p4 * 2 + u], aC[mt], &bB[p4][u * 2]);
    }

    // weighting -> G fp16
    int crow = lane >> 2, ccol = (lane & 3) * 2;
#pragma unroll
    for (int mt = 0; mt < 2; mt++) {
        int t0 = wm + mt * 16 + crow, t1 = t0 + 8;
        float ct0 = sCum[t0], ct1 = sCum[t1];
#pragma unroll
        for (int nt = 0; nt < 8; nt++) {
            int s0 = wn + nt * 8 + ccol, s1 = s0 + 1;
            float cs0 = sCum[s0], cs1 = sCum[s1];
            float d0 = sDt[s0], d1 = sDt[s1];
            float v0 = (s0 <= t0) ? __expf(ct0 - cs0) * d0 * sacc[mt][nt][0] : 0.f;
            float v1 = (s1 <= t0) ? __expf(ct0 - cs1) * d1 * sacc[mt][nt][1] : 0.f;
            float v2 = (s0 <= t1) ? __expf(ct1 - cs0) * d0 * sacc[mt][nt][2] : 0.f;
            float v3 = (s1 <= t1) ? __expf(ct1 - cs1) * d1 * sacc[mt][nt][3] : 0.f;
            *(__half2*)(sG + t0 * XT_STR + s0) = __floats2half2_rn(v0, v1);
            *(__half2*)(sG + t1 * XT_STR + s0) = __floats2half2_rn(v2, v3);
        }
    }
#pragma unroll
    for (int jj = 0; jj < 8; jj++) {
        int e = tid + jj * 256;
        int t = e >> 4, n = e & 15;
        sG[t * XT_STR + 128 + n] =
            __float2half_rn(__expf(sCum[t]) * __half2float(sC[t * SCB_STR + n]));
    }
    __syncthreads();

    // phase B: Y = G @ X'
    int wm2 = (wid & 3) * 32, wn2 = (wid >> 2) * 32;
    float acc2[2][4][4];
#pragma unroll
    for (int i = 0; i < 2; i++)
#pragma unroll
        for (int j = 0; j < 4; j++)
#pragma unroll
            for (int q = 0; q < 4; q++) acc2[i][j][q] = 0.f;
    {
        int lr = lane & 15;
        int q = lane >> 3, rr = lane & 7;
        uint32_t aOff2[2], bOff2[2];
#pragma unroll
        for (int mt = 0; mt < 2; mt++)
            aOff2[mt] = sb + OFF_G + (uint32_t)((wm2 + mt * 16 + lr) * (XT_STR * 2) + (lane >> 4) * 16);
#pragma unroll
        for (int pp = 0; pp < 2; pp++) {
            int row = wn2 + pp * 16 + (q >> 1) * 8 + rr;
            bOff2[pp] = sb + OFF_XT + (uint32_t)(row * (XT_STR * 2) + (q & 1) * 16);
        }
#pragma unroll
        for (int k9 = 0; k9 < 9; k9++) {
            uint32_t kb = (uint32_t)(k9 * 32);
            uint32_t aG[2][4], bX[2][4];
#pragma unroll
            for (int mt = 0; mt < 2; mt++)
                ldsm_x4(aG[mt], aOff2[mt] + kb);
#pragma unroll
            for (int pp = 0; pp < 2; pp++)
                ldsm_x4(bX[pp], bOff2[pp] + kb);
#pragma unroll
            for (int mt = 0; mt < 2; mt++)
#pragma unroll
                for (int pp = 0; pp < 2; pp++)
#pragma unroll
                    for (int u = 0; u < 2; u++)
                        mma16816(acc2[mt][pp * 2 + u], aG[mt], &bX[pp][u * 2]);
        }
    }
    __syncthreads();

    float Dh = Dp[h];
#pragma unroll
    for (int mt = 0; mt < 2; mt++)
#pragma unroll
        for (int nt = 0; nt < 4; nt++) {
            int t0 = wm2 + mt * 16 + crow, t1 = t0 + 8;
            int p0 = wn2 + nt * 8 + ccol, p1 = p0 + 1;
            sYf[t0 * 68 + p0] = acc2[mt][nt][0] + Dh * __half2float(sXT[p0 * XT_STR + t0]);
            sYf[t0 * 68 + p1] = acc2[mt][nt][1] + Dh * __half2float(sXT[p1 * XT_STR + t0]);
            sYf[t1 * 68 + p0] = acc2[mt][nt][2] + Dh * __half2float(sXT[p0 * XT_STR + t1]);
            sYf[t1 * 68 + p1] = acc2[mt][nt][3] + Dh * __half2float(sXT[p1 * XT_STR + t1]);
        }
    __syncthreads();
#pragma unroll
    for (int jj = 0; jj < 32; jj++) {
        int e = tid + jj * 256;
        int r = e >> 6, p = e & 63;
        g_Y[(rowbase + r) * DINNERX + h * 64 + p] = __float2half_rn(sYf[r * 68 + p]);
    }
}

// --------------------------- gated rmsnorm (fp16 Y) --------------------------
__global__ void gatednorm_kernel(const float* __restrict__ gnw)
{
    int warp = (blockIdx.x * blockDim.x + threadIdx.x) >> 5;
    int lane = threadIdx.x & 31;
    if (warp >= BT) return;
    const __half* yr = g_Y + (size_t)warp * DINNERX;
    const float4* gr = (const float4*)(g_PROJ + (size_t)warp * PROJD);
    __half yh[8];
    *(uint4*)yh = *(const uint4*)(yr + lane * 8);
    float v[8];
    float ss = 0.f;
#pragma unroll
    for (int q = 0; q < 2; q++) {
        float4 gv = gr[lane * 2 + q];
        float gy[4] = { gv.x, gv.y, gv.z, gv.w };
#pragma unroll
        for (int i = 0; i < 4; i++) {
            float s = gy[i] / (1.f + __expf(-gy[i]));
            float t = __half2float(yh[q * 4 + i]) * s;
            v[q * 4 + i] = t;
            ss += t * t;
        }
    }
#pragma unroll
    for (int o = 16; o; o >>= 1) ss += __shfl_xor_sync(0xffffffffu, ss, o);
    float r = rsqrtf(ss * (1.f / DINNERX) + EPSF);
    size_t base = (size_t)warp * DINNERX + lane * 8;
    __half h[8];
#pragma unroll
    for (int i = 0; i < 8; i++) h[i] = __float2half_rn(v[i] * r * gnw[lane * 8 + i]);
    *(uint4*)(g_ynh + base) = *(uint4*)h;
}

// ---------------------------- final pool + head ------------------------------
__global__ __launch_bounds__(256) void pool_kernel(const float* __restrict__ nfw)
{
    int b = blockIdx.y;
    int chunk = blockIdx.x;            // 0..3
    int wid = threadIdx.x >> 5, lane = threadIdx.x & 31;
    float4 wnf = *(const float4*)(nfw + lane * 4);
    float4 acc = make_float4(0.f, 0.f, 0.f, 0.f);
    int t0 = chunk * 512 + wid * 64;
    for (int r = 0; r < 64; r++) {
        int t = t0 + r;
        float4 v = *(const float4*)(g_H + (size_t)(b * TT + t) * DMX + lane * 4);
        float ss = v.x*v.x + v.y*v.y + v.z*v.z + v.w*v.w;
#pragma unroll
        for (int o = 16; o; o >>= 1) ss += __shfl_xor_sync(0xffffffffu, ss, o);
        float rv = rsqrtf(ss * (1.f / DMX) + EPSF);
        acc.x += v.x * rv; acc.y += v.y * rv;
        acc.z += v.z * rv; acc.w += v.w * rv;
    }
    float inv = 1.f / TT;
    acc.x *= inv * wnf.x; acc.y *= inv * wnf.y;
    acc.z *= inv * wnf.z; acc.w *= inv * wnf.w;
    *(float4*)(g_POOLP + (size_t)(b * 32 + chunk * 8 + wid) * DMX + lane * 4) = acc;
}

__global__ void final_kernel(const float* __restrict__ ow,
                             const float* __restrict__ ob,
                             float* __restrict__ out)
{
    int b = blockIdx.x;
    int j = threadIdx.x;
    __shared__ float p[DMX];
    if (j < DMX) {
        float s = 0.f;
#pragma unroll 8
        for (int k = 0; k < 32; k++) s += g_POOLP[(size_t)(b * 32 + k) * DMX + j];
        p[j] = s;
    }
    __syncthreads();
    float acc = ob[j];
#pragma unroll 4
    for (int k = 0; k < DMX; k++) acc += p[k] * ow[k * DIMX + j];
    out[b * DIMX + j] = acc;
}

// ------------------------------ launcher -------------------------------------
extern "C" void kernel_launch(void* const* d_in, const int* in_sizes, int n_in,
                              void* d_out, int out_size)
{
    const float* x         = (const float*)d_in[0];
    const float* in_w      = (const float*)d_in[1];
    const float* in_b      = (const float*)d_in[2];
    const float* norm_w    = (const float*)d_in[3];
    const float* inproj_w  = (const float*)d_in[4];
    const float* conv_w    = (const float*)d_in[5];
    const float* conv_b    = (const float*)d_in[6];
    const float* A_log     = (const float*)d_in[7];
    const float* Dparam    = (const float*)d_in[8];
    const float* dt_bias   = (const float*)d_in[9];
    const float* gnorm_w   = (const float*)d_in[10];
    const float* outproj_w = (const float*)d_in[11];
    const float* normf_w   = (const float*)d_in[12];
    const float* out_w     = (const float*)d_in[13];
    const float* out_b     = (const float*)d_in[14];

    float *pH, *pPROJ;
    __half *pXh, *pHNh, *pYNh, *pW1, *pW2, *pW3;
    cudaGetSymbolAddress((void**)&pH,    g_H);
    cudaGetSymbolAddress((void**)&pPROJ, g_PROJ);
    cudaGetSymbolAddress((void**)&pXh,   g_xh);
    cudaGetSymbolAddress((void**)&pHNh,  g_hnh);
    cudaGetSymbolAddress((void**)&pYNh,  g_ynh);
    cudaGetSymbolAddress((void**)&pW1,   g_w1h);
    cudaGetSymbolAddress((void**)&pW2,   g_w2h);
    cudaGetSymbolAddress((void**)&pW3,   g_w3h);

    cudaFuncSetAttribute(mma_gemm_proj, cudaFuncAttributeMaxDynamicSharedMemorySize, SM_TOTAL);
    cudaFuncSetAttribute(mma_gemm_dm<0,true>,  cudaFuncAttributeMaxDynamicSharedMemorySize, SM_TOTAL);
    cudaFuncSetAttribute(mma_gemm_dm<2,true>,  cudaFuncAttributeMaxDynamicSharedMemorySize, SM_TOTAL);
    cudaFuncSetAttribute(mma_gemm_dm<2,false>, cudaFuncAttributeMaxDynamicSharedMemorySize, SM_TOTAL);
    cudaFuncSetAttribute(ssd_mma_kernel, cudaFuncAttributeMaxDynamicSharedMemorySize, SSD_SMEM);

    prep_kernel<<<(PREP_N + 255) / 256, 256>>>(x, in_w, inproj_w, outproj_w);

    // h = x @ in_w + in_b ; fused rmsnorm(l=0) -> hn
    mma_gemm_dm<0,true><<<BT / 64, 256, SM_TOTAL>>>(
        pXh, pW1, in_b, norm_w, pH, pHNh, DIMX);

    for (int l = 0; l < LNUM; l++) {
        mma_gemm_proj<<<dim3(PROJPAD / 64, BT / 128), 256, SM_TOTAL>>>(
            pHNh, pW2 + (size_t)l * PROJPAD * DMX, pPROJ, PROJD, DMX);
        conv_kernel<<<dim3(TT / 64, BB), 288>>>(
            conv_w + l * CONVD * 4, conv_b + l * CONVD);
        chunkstate_kernel<<<dim3(NCHK, BHX), 256>>>(A_log + l * NHX, dt_bias + l * NHX);
        ssd_mma_kernel<<<dim3(NCHK, BHX), 256, SSD_SMEM>>>(Dparam + l * NHX);
        gatednorm_kernel<<<BT / 8, 256>>>(gnorm_w + l * DINNERX);
        if (l == 0)
            mma_gemm_dm<2,true><<<BT / 64, 256, SM_TOTAL>>>(
                pYNh, pW3, nullptr, norm_w + DMX, pH, pHNh, DINNERX);
        else
            mma_gemm_dm<2,false><<<BT / 64, 256, SM_TOTAL>>>(
                pYNh, pW3 + (size_t)DMX * DINNERX, nullptr, nullptr, pH, nullptr, DINNERX);
    }

    pool_kernel<<<dim3(4, BB), 256>>>(normf_w);
    final_kernel<<<BB, DIMX>>>(out_w, out_b, (float*)d_out);
}

// round 16
// speedup vs baseline: 1.1083x; 1.1083x over previous
#include <cuda_runtime.h>
#include <cuda_fp16.h>
#include <math.h>
#include <stdint.h>

#define BB 8
#define TT 2048
#define DIMX 512
#define DMX 128
#define DINNERX 256
#define NSTATEX 16
#define HDIMX 64
#define NHX 4
#define CONVD 288
#define PROJD 548
#define PROJPAD 576
#define LNUM 2
#define BT (BB*TT)          // 16384
#define QC 128
#define NCHK (TT/QC)        // 16
#define BHX (BB*NHX)        // 32
#define EPSF 1e-5f

// ------------------------- scratch (static device memory) -------------------
__device__ float g_H[BT*DMX];
__device__ float g_PROJ[BT*PROJD];
__device__ __half g_CONVX[BT*CONVD];
__device__ float g_DT[BHX*TT];
__device__ float g_CUM[BHX*TT];
__device__ float g_SLOC[BHX*NCHK*HDIMX*NSTATEX];
__device__ __half g_Y[BT*DINNERX];
__device__ float g_POOLP[BB*32*DMX];

__device__ __half g_xh[BT*DIMX];
__device__ __half g_hnh[BT*DMX];
__device__ __half g_ynh[BT*DINNERX];
__device__ __half g_w1h[DMX*DIMX];                 // in_w^T [128][512]
__device__ __half g_w2h[LNUM*PROJPAD*DMX];         // inproj^T [576][128]
__device__ __half g_w3h[LNUM*DMX*DINNERX];         // outproj^T [128][256]

// ------------------------------ PTX helpers ---------------------------------
__device__ __forceinline__ uint32_t smem_u32(const void* p) {
    uint32_t a;
    asm("{ .reg .u64 t; cvta.to.shared.u64 t, %1; cvt.u32.u64 %0, t; }" : "=r"(a) : "l"(p));
    return a;
}
__device__ __forceinline__ void ldsm_x4(uint32_t* r, uint32_t addr) {
    asm volatile("ldmatrix.sync.aligned.m8n8.x4.shared.b16 {%0,%1,%2,%3}, [%4];"
        : "=r"(r[0]), "=r"(r[1]), "=r"(r[2]), "=r"(r[3]) : "r"(addr));
}
__device__ __forceinline__ void mma16816(float* c, const uint32_t* a, const uint32_t* b) {
    asm volatile("mma.sync.aligned.m16n8k16.row.col.f32.f16.f16.f32 "
        "{%0,%1,%2,%3}, {%4,%5,%6,%7}, {%8,%9}, {%0,%1,%2,%3};"
        : "+f"(c[0]), "+f"(c[1]), "+f"(c[2]), "+f"(c[3])
        : "r"(a[0]), "r"(a[1]), "r"(a[2]), "r"(a[3]), "r"(b[0]), "r"(b[1]));
}
__device__ __forceinline__ void cp16(uint32_t saddr, const void* g) {
    asm volatile("cp.async.ca.shared.global [%0], [%1], 16;" :: "r"(saddr), "l"(g));
}
__device__ __forceinline__ void cp_commit() {
    asm volatile("cp.async.commit_group;" ::: "memory");
}
template<int N> __device__ __forceinline__ void cp_wait() {
    asm volatile("cp.async.wait_group %0;" :: "n"(N) : "memory");
}

// ------------------------------ HMMA GEMM (1-term fp16) ----------------------
#define LDSA 72
#define A_BYTES (128*LDSA*2)                 // 18432
#define B_BYTES (64*LDSA*2)                  // 9216
#define OFF_B A_BYTES
#define STAGE_BYTES (A_BYTES + B_BYTES)      // 27648
#define SM_TOTAL (2*STAGE_BYTES)             // 55296

template<int MODE>   // 0: C=D+bias ; 1: C=D ; 2: C+=D
__global__ __launch_bounds__(256, 2) void mma_gemm(
    const __half* __restrict__ A, const __half* __restrict__ Wt,
    const float* __restrict__ bias, float* __restrict__ C,
    int N, int K)
{
    extern __shared__ char smem[];
    uint32_t sb = smem_u32(smem);
    int tid = threadIdx.x, wid = tid >> 5, lane = tid & 31;
    int m0 = blockIdx.y * 128, n0 = blockIdx.x * 64;
    int wm = (wid & 3) * 32, wn = (wid >> 2) * 32;

    float acc[2][4][4];
#pragma unroll
    for (int i = 0; i < 2; i++)
#pragma unroll
        for (int j = 0; j < 4; j++)
#pragma unroll
            for (int q = 0; q < 4; q++) acc[i][j][q] = 0.f;

    int lr = lane & 15;
    uint32_t aOff[2];
#pragma unroll
    for (int mt = 0; mt < 2; mt++)
        aOff[mt] = (uint32_t)((wm + mt * 16 + lr) * (LDSA * 2) + (lane >> 4) * 16);
    uint32_t bOff[2];
    {
        int q = lane >> 3, rr = lane & 7;
#pragma unroll
        for (int p = 0; p < 2; p++) {
            int row = wn + p * 16 + (q >> 1) * 8 + rr;
            bOff[p] = (uint32_t)(OFF_B + row * (LDSA * 2) + (q & 1) * 16);
        }
    }

    int nstage = K >> 6;
    auto load_stage = [&](int buf, int k0) {
        uint32_t base = sb + buf * STAGE_BYTES;
#pragma unroll
        for (int i = 0; i < 4; i++) {
            int li = tid + i * 256;
            int r = li >> 3, g8 = li & 7;
            uint32_t so = (uint32_t)(r * (LDSA * 2) + g8 * 16);
            cp16(base + so, A + (size_t)(m0 + r) * K + k0 + g8 * 8);
        }
#pragma unroll
        for (int i = 0; i < 2; i++) {
            int li = tid + i * 256;
            int r = li >> 3, g8 = li & 7;
            uint32_t so = (uint32_t)(r * (LDSA * 2) + g8 * 16);
            cp16(base + OFF_B + so, Wt + (size_t)(n0 + r) * K + k0 + g8 * 8);
        }
    };

    load_stage(0, 0);
    cp_commit();

    for (int s = 0; s < nstage; s++) {
        if (s + 1 < nstage) load_stage((s + 1) & 1, (s + 1) * 64);
        cp_commit();
        if (s + 1 < nstage) cp_wait<1>(); else cp_wait<0>();
        __syncthreads();

        uint32_t sbuf = sb + (s & 1) * STAGE_BYTES;
#pragma unroll
        for (int ks = 0; ks < 64; ks += 16) {
            uint32_t kb = (uint32_t)(ks * 2);
            uint32_t ah[2][4], b4[2][4];
#pragma unroll
            for (int mt = 0; mt < 2; mt++)
                ldsm_x4(ah[mt], sbuf + aOff[mt] + kb);
#pragma unroll
            for (int p = 0; p < 2; p++)
                ldsm_x4(b4[p], sbuf + bOff[p] + kb);
#pragma unroll
            for (int mt = 0; mt < 2; mt++)
#pragma unroll
                for (int p = 0; p < 2; p++)
#pragma unroll
                    for (int u = 0; u < 2; u++)
                        mma16816(acc[mt][2 * p + u], ah[mt], &b4[p][u * 2]);
        }
        __syncthreads();
    }

    float* S = (float*)smem;          // [128][68]
    const int SW = 68;
    int crow = lane >> 2, ccol = (lane & 3) * 2;
#pragma unroll
    for (int mt = 0; mt < 2; mt++)
#pragma unroll
        for (int nt = 0; nt < 4; nt++) {
            int r = wm + mt * 16 + crow;
            int cc = wn + nt * 8 + ccol;
            S[r * SW + cc]           = acc[mt][nt][0];
            S[r * SW + cc + 1]       = acc[mt][nt][1];
            S[(r + 8) * SW + cc]     = acc[mt][nt][2];
            S[(r + 8) * SW + cc + 1] = acc[mt][nt][3];
        }
    __syncthreads();
#pragma unroll
    for (int it = 0; it < 32; it++) {
        int li = tid + it * 256;
        int cc = li & 63, r = li >> 6;
        int col = n0 + cc;
        if (col < N) {
            float v = S[r * SW + cc];
            if (MODE == 0) v += bias[col];
            size_t o = (size_t)(m0 + r) * N + col;
            if (MODE == 2) v += C[o];
            C[o] = v;
        }
    }
}

// --------------------------- fused prep (x split + weight transposes) --------
#define XN4 (BT*DIMX/4)
#define TS_R1 (DMX*DIMX)
#define TS_R2 (LNUM*PROJPAD*DMX)
#define TS_R3 (LNUM*DMX*DINNERX)
#define PREP_N (XN4 + TS_R1 + TS_R2 + TS_R3)
__global__ void prep_kernel(const float* __restrict__ x,
                            const float* __restrict__ in_w,
                            const float* __restrict__ inproj_w,
                            const float* __restrict__ outproj_w)
{
    int idx = blockIdx.x * blockDim.x + threadIdx.x;
    if (idx < XN4) {
        float4 v = ((const float4*)x)[idx];
        __half h[4] = { __float2half_rn(v.x), __float2half_rn(v.y),
                        __float2half_rn(v.z), __float2half_rn(v.w) };
        *(uint2*)(g_xh + (size_t)idx * 4) = *(uint2*)h;
        return;
    }
    idx -= XN4;
    if (idx < TS_R1) {
        int n = idx / DIMX, k = idx % DIMX;
        g_w1h[idx] = __float2half_rn(in_w[(size_t)k * DMX + n]);
        return;
    }
    idx -= TS_R1;
    if (idx < TS_R2) {
        int l = idx / (PROJPAD * DMX), r = idx % (PROJPAD * DMX);
        int n = r / DMX, k = r % DMX;
        float v = (n < PROJD) ? inproj_w[(size_t)l * DMX * PROJD + (size_t)k * PROJD + n] : 0.f;
        g_w2h[idx] = __float2half_rn(v);
        return;
    }
    idx -= TS_R2;
    if (idx < TS_R3) {
        int l = idx / (DMX * DINNERX), r = idx % (DMX * DINNERX);
        int n = r / DINNERX, k = r % DINNERX;
        g_w3h[idx] = __float2half_rn(outproj_w[(size_t)l * DINNERX * DMX + (size_t)k * DMX + n]);
    }
}

// ------------------------------ rmsnorm (DM=128) -----------------------------
__global__ void rmsnorm128_kernel(const float* __restrict__ src,
                                  const float* __restrict__ w,
                                  __half* __restrict__ dst)
{
    int warp = (blockIdx.x * blockDim.x + threadIdx.x) >> 5;
    int lane = threadIdx.x & 31;
    if (warp >= BT) return;
    const float* row = src + (size_t)warp * DMX;
    float4 v = *(const float4*)(row + lane * 4);
    float ss = v.x*v.x + v.y*v.y + v.z*v.z + v.w*v.w;
#pragma unroll
    for (int o = 16; o; o >>= 1) ss += __shfl_xor_sync(0xffffffffu, ss, o);
    float r = rsqrtf(ss * (1.f / DMX) + EPSF);
    float4 wv = *(const float4*)(w + lane * 4);
    __half h[4] = { __float2half_rn(v.x*r*wv.x), __float2half_rn(v.y*r*wv.y),
                    __float2half_rn(v.z*r*wv.z), __float2half_rn(v.w*r*wv.w) };
    *(uint2*)(dst + (size_t)warp * DMX + lane * 4) = *(uint2*)h;
}

// ------------------------ causal conv + silu (32 t/block) --------------------
__global__ __launch_bounds__(288) void conv_kernel(const float* __restrict__ cw,
                                                   const float* __restrict__ cb)
{
    int b = blockIdx.y;
    int t0 = blockIdx.x * 32;
    int c = threadIdx.x;
    float w0 = cw[c*4], w1 = cw[c*4+1], w2 = cw[c*4+2], w3 = cw[c*4+3];
    float bias = cb[c];
    size_t base = (size_t)(b * TT) * PROJD + DINNERX + c;
    float xm3 = 0.f, xm2 = 0.f, xm1 = 0.f;
    if (t0 >= 3) {
        xm3 = g_PROJ[base + (size_t)(t0-3) * PROJD];
        xm2 = g_PROJ[base + (size_t)(t0-2) * PROJD];
        xm1 = g_PROJ[base + (size_t)(t0-1) * PROJD];
    }
    for (int i = 0; i < 4; i++) {
        float xv[8];
#pragma unroll
        for (int j = 0; j < 8; j++)
            xv[j] = g_PROJ[base + (size_t)(t0 + i*8 + j) * PROJD];
#pragma unroll
        for (int j = 0; j < 8; j++) {
            float a = bias + w0*xm3 + w1*xm2 + w2*xm1 + w3*xv[j];
            g_CONVX[(size_t)(b * TT + t0 + i*8 + j) * CONVD + c] =
                __float2half_rn(a / (1.f + __expf(-a)));
            xm3 = xm2; xm2 = xm1; xm1 = xv[j];
        }
    }
}

// ---------------- chunkstate (fused softplus + cumsum + local state) ---------
__global__ __launch_bounds__(256) void chunkstate_kernel(const float* __restrict__ Alog,
                                                         const float* __restrict__ dtb)
{
    int c = blockIdx.x, bh = blockIdx.y;
    int b = bh >> 2, h = bh & 3;
    int tid = threadIdx.x;
    __shared__ float sc[QC];
    __shared__ float sdt[QC];
    __shared__ float coef[QC];
    __shared__ float Xs[16][HDIMX];
    __shared__ float Bsh[16][NSTATEX];
    int cbase = bh * TT + c * QC;
    size_t rowbase = (size_t)(b * TT + c * QC);

    float Ah = -__expf(Alog[h]);
    if (tid < QC) {
        float v = g_PROJ[(size_t)(b * TT + c * QC + tid) * PROJD + DINNERX + CONVD + h] + dtb[h];
        float sp = (v > 20.f) ? v : log1pf(__expf(v));
        sdt[tid] = sp;
        sc[tid] = sp * Ah;
    }
    __syncthreads();
#pragma unroll
    for (int off = 1; off < QC; off <<= 1) {
        float x = 0.f;
        if (tid < QC && tid >= off) x = sc[tid - off];
        __syncthreads();
        if (tid < QC) sc[tid] += x;
        __syncthreads();
    }
    if (tid < QC) {
        g_DT[cbase + tid]  = sdt[tid];
        g_CUM[cbase + tid] = sc[tid];
        coef[tid] = __expf(sc[QC - 1] - sc[tid]) * sdt[tid];
    }

    float acc[4] = {0.f, 0.f, 0.f, 0.f};
    int p = tid >> 2, ng = (tid & 3) * 4;
    for (int tt = 0; tt < QC; tt += 16) {
        __syncthreads();
#pragma unroll
        for (int j = 0; j < 4; j++) {
            int li = tid + j * 256;
            int r = li >> 6, pp = li & 63;
            Xs[r][pp] = __half2float(g_CONVX[(rowbase + tt + r) * CONVD + h * 64 + pp]);
        }
        {
            int r = tid >> 4, n = tid & 15;
            Bsh[r][n] = __half2float(g_CONVX[(rowbase + tt + r) * CONVD + 256 + n]);
        }
        __syncthreads();
#pragma unroll
        for (int r = 0; r < 16; r++) {
            float cx = coef[tt + r] * Xs[r][p];
#pragma unroll
            for (int j = 0; j < 4; j++) acc[j] += cx * Bsh[r][ng + j];
        }
    }
    size_t dst = ((size_t)bh * NCHK + c) * (HDIMX * NSTATEX) + p * NSTATEX + ng;
    *(float4*)(g_SLOC + dst) = make_float4(acc[0], acc[1], acc[2], acc[3]);
}

// ============================ SSD via HMMA ===================================
#define SCB_STR 24
#define XT_STR 152
#define OFF_SC 0
#define OFF_SB 6144
#define OFF_XT 12288
#define OFF_G  31744
#define OFF_CUM 70656
#define OFF_SDT 71168
#define SSD_SMEM 71680

__global__ __launch_bounds__(256, 2) void ssd_mma_kernel(const float* __restrict__ Dp)
{
    extern __shared__ char sm[];
    __half* sC  = (__half*)(sm + OFF_SC);
    __half* sB  = (__half*)(sm + OFF_SB);
    __half* sXT = (__half*)(sm + OFF_XT);
    __half* sG  = (__half*)(sm + OFF_G);
    float*  sCum = (float*)(sm + OFF_CUM);
    float*  sDt  = (float*)(sm + OFF_SDT);
    float*  sYf  = (float*)(sm + OFF_G);
    uint32_t sb = smem_u32(sm);

    int c = blockIdx.x, bh = blockIdx.y;
    int b = bh >> 2, h = bh & 3;
    int tid = threadIdx.x, wid = tid >> 5, lane = tid & 31;
    size_t rowbase = (size_t)(b * TT + c * QC);
    int cbase = bh * TT + c * QC;

    if (tid < QC) { sCum[tid] = g_CUM[cbase + tid]; sDt[tid] = g_DT[cbase + tid]; }
#pragma unroll
    for (int jj = 0; jj < 8; jj++) {
        int e = tid + jj * 256;
        int r = e >> 4, n = e & 15;
        sC[r * SCB_STR + n] = g_CONVX[(rowbase + r) * CONVD + 272 + n];
        sB[r * SCB_STR + n] = g_CONVX[(rowbase + r) * CONVD + 256 + n];
    }
#pragma unroll
    for (int jj = 0; jj < 32; jj++) {
        int e = tid + jj * 256;
        int s = e >> 6, p = e & 63;
        sXT[p * XT_STR + s] = g_CONVX[(rowbase + s) * CONVD + h * 64 + p];
    }
    {
        size_t sbase = (size_t)bh * NCHK * (HDIMX * NSTATEX);
        int i = tid * 4;
        float4 s4 = make_float4(0.f, 0.f, 0.f, 0.f);
        for (int j = 0; j < c; j++) {
            float dj = __expf(g_CUM[bh * TT + j * QC + QC - 1]);
            float4 a = *(const float4*)(g_SLOC + sbase + j * (HDIMX * NSTATEX) + i);
            s4.x = s4.x * dj + a.x; s4.y = s4.y * dj + a.y;
            s4.z = s4.z * dj + a.z; s4.w = s4.w * dj + a.w;
        }
        int p = i >> 4, n0 = i & 15;
        __half hv[4] = { __float2half_rn(s4.x), __float2half_rn(s4.y),
                         __float2half_rn(s4.z), __float2half_rn(s4.w) };
        *(uint2*)(sXT + p * XT_STR + 128 + n0) = *(uint2*)hv;
    }
    __syncthreads();

    // phase A: S = C @ B^T
    int wm = (wid & 3) * 32, wn = (wid >> 2) * 64;
    float sacc[2][8][4];
#pragma unroll
    for (int i = 0; i < 2; i++)
#pragma unroll
        for (int j = 0; j < 8; j++)
#pragma unroll
            for (int q = 0; q < 4; q++) sacc[i][j][q] = 0.f;
    {
        uint32_t aC[2][4], bB[4][4];
        int lr = lane & 15;
#pragma unroll
        for (int mt = 0; mt < 2; mt++)
            ldsm_x4(aC[mt], sb + OFF_SC + (uint32_t)((wm + mt * 16 + lr) * (SCB_STR * 2) + (lane >> 4) * 16));
        int q = lane >> 3, rr = lane & 7;
#pragma unroll
        for (int p4 = 0; p4 < 4; p4++) {
            int row = wn + p4 * 16 + (q >> 1) * 8 + rr;
            ldsm_x4(bB[p4], sb + OFF_SB + (uint32_t)(row * (SCB_STR * 2) + (q & 1) * 16));
        }
#pragma unroll
        for (int mt = 0; mt < 2; mt++)
#pragma unroll
            for (int p4 = 0; p4 < 4; p4++)
#pragma unroll
                for (int u = 0; u < 2; u++)
                    mma16816(sacc[mt][p4 * 2 + u], aC[mt], &bB[p4][u * 2]);
    }

    // weighting -> G fp16
    int crow = lane >> 2, ccol = (lane & 3) * 2;
#pragma unroll
    for (int mt = 0; mt < 2; mt++) {
        int t0 = wm + mt * 16 + crow, t1 = t0 + 8;
        float ct0 = sCum[t0], ct1 = sCum[t1];
#pragma unroll
        for (int nt = 0; nt < 8; nt++) {
            int s0 = wn + nt * 8 + ccol, s1 = s0 + 1;
            float cs0 = sCum[s0], cs1 = sCum[s1];
            float d0 = sDt[s0], d1 = sDt[s1];
            float v0 = (s0 <= t0) ? __expf(ct0 - cs0) * d0 * sacc[mt][nt][0] : 0.f;
            float v1 = (s1 <= t0) ? __expf(ct0 - cs1) * d1 * sacc[mt][nt][1] : 0.f;
            float v2 = (s0 <= t1) ? __expf(ct1 - cs0) * d0 * sacc[mt][nt][2] : 0.f;
            float v3 = (s1 <= t1) ? __expf(ct1 - cs1) * d1 * sacc[mt][nt][3] : 0.f;
            *(__half2*)(sG + t0 * XT_STR + s0) = __floats2half2_rn(v0, v1);
            *(__half2*)(sG + t1 * XT_STR + s0) = __floats2half2_rn(v2, v3);
        }
    }
#pragma unroll
    for (int jj = 0; jj < 8; jj++) {
        int e = tid + jj * 256;
        int t = e >> 4, n = e & 15;
        sG[t * XT_STR + 128 + n] =
            __float2half_rn(__expf(sCum[t]) * __half2float(sC[t * SCB_STR + n]));
    }
    __syncthreads();

    // phase B: Y = G @ X'
    int wm2 = (wid & 3) * 32, wn2 = (wid >> 2) * 32;
    float acc2[2][4][4];
#pragma unroll
    for (int i = 0; i < 2; i++)
#pragma unroll
        for (int j = 0; j < 4; j++)
#pragma unroll
            for (int q = 0; q < 4; q++) acc2[i][j][q] = 0.f;
    {
        int lr = lane & 15;
        int q = lane >> 3, rr = lane & 7;
        uint32_t aOff2[2], bOff2[2];
#pragma unroll
        for (int mt = 0; mt < 2; mt++)
            aOff2[mt] = sb + OFF_G + (uint32_t)((wm2 + mt * 16 + lr) * (XT_STR * 2) + (lane >> 4) * 16);
#pragma unroll
        for (int pp = 0; pp < 2; pp++) {
            int row = wn2 + pp * 16 + (q >> 1) * 8 + rr;
            bOff2[pp] = sb + OFF_XT + (uint32_t)(row * (XT_STR * 2) + (q & 1) * 16);
        }
#pragma unroll
        for (int k9 = 0; k9 < 9; k9++) {
            uint32_t kb = (uint32_t)(k9 * 32);
            uint32_t aG[2][4], bX[2][4];
#pragma unroll
            for (int mt = 0; mt < 2; mt++)
                ldsm_x4(aG[mt], aOff2[mt] + kb);
#pragma unroll
            for (int pp = 0; pp < 2; pp++)
                ldsm_x4(bX[pp], bOff2[pp] + kb);
#pragma unroll
            for (int mt = 0; mt < 2; mt++)
#pragma unroll
                for (int pp = 0; pp < 2; pp++)
#pragma unroll
                    for (int u = 0; u < 2; u++)
                        mma16816(acc2[mt][pp * 2 + u], aG[mt], &bX[pp][u * 2]);
        }
    }
    __syncthreads();

    float Dh = Dp[h];
#pragma unroll
    for (int mt = 0; mt < 2; mt++)
#pragma unroll
        for (int nt = 0; nt < 4; nt++) {
            int t0 = wm2 + mt * 16 + crow, t1 = t0 + 8;
            int p0 = wn2 + nt * 8 + ccol, p1 = p0 + 1;
            sYf[t0 * 68 + p0] = acc2[mt][nt][0] + Dh * __half2float(sXT[p0 * XT_STR + t0]);
            sYf[t0 * 68 + p1] = acc2[mt][nt][1] + Dh * __half2float(sXT[p1 * XT_STR + t0]);
            sYf[t1 * 68 + p0] = acc2[mt][nt][2] + Dh * __half2float(sXT[p0 * XT_STR + t1]);
            sYf[t1 * 68 + p1] = acc2[mt][nt][3] + Dh * __half2float(sXT[p1 * XT_STR + t1]);
        }
    __syncthreads();
#pragma unroll
    for (int jj = 0; jj < 32; jj++) {
        int e = tid + jj * 256;
        int r = e >> 6, p = e & 63;
        g_Y[(rowbase + r) * DINNERX + h * 64 + p] = __float2half_rn(sYf[r * 68 + p]);
    }
}

// --------------------------- gated rmsnorm (fp16 Y) --------------------------
__global__ void gatednorm_kernel(const float* __restrict__ gnw)
{
    int warp = (blockIdx.x * blockDim.x + threadIdx.x) >> 5;
    int lane = threadIdx.x & 31;
    if (warp >= BT) return;
    const __half* yr = g_Y + (size_t)warp * DINNERX;
    const float4* gr = (const float4*)(g_PROJ + (size_t)warp * PROJD);
    __half yh[8];
    *(uint4*)yh = *(const uint4*)(yr + lane * 8);
    float v[8];
    float ss = 0.f;
#pragma unroll
    for (int q = 0; q < 2; q++) {
        float4 gv = gr[lane * 2 + q];
        float gy[4] = { gv.x, gv.y, gv.z, gv.w };
#pragma unroll
        for (int i = 0; i < 4; i++) {
            float s = gy[i] / (1.f + __expf(-gy[i]));
            float t = __half2float(yh[q * 4 + i]) * s;
            v[q * 4 + i] = t;
            ss += t * t;
        }
    }
#pragma unroll
    for (int o = 16; o; o >>= 1) ss += __shfl_xor_sync(0xffffffffu, ss, o);
    float r = rsqrtf(ss * (1.f / DINNERX) + EPSF);
    size_t base = (size_t)warp * DINNERX + lane * 8;
    __half h[8];
#pragma unroll
    for (int i = 0; i < 8; i++) h[i] = __float2half_rn(v[i] * r * gnw[lane * 8 + i]);
    *(uint4*)(g_ynh + base) = *(uint4*)h;
}

// ---------------------------- final pool + head ------------------------------
__global__ __launch_bounds__(256) void pool_kernel(const float* __restrict__ nfw)
{
    int b = blockIdx.y;
    int chunk = blockIdx.x;            // 0..3
    int wid = threadIdx.x >> 5, lane = threadIdx.x & 31;
    float4 wnf = *(const float4*)(nfw + lane * 4);
    float4 acc = make_float4(0.f, 0.f, 0.f, 0.f);
    int t0 = chunk * 512 + wid * 64;
    for (int r = 0; r < 64; r++) {
        int t = t0 + r;
        float4 v = *(const float4*)(g_H + (size_t)(b * TT + t) * DMX + lane * 4);
        float ss = v.x*v.x + v.y*v.y + v.z*v.z + v.w*v.w;
#pragma unroll
        for (int o = 16; o; o >>= 1) ss += __shfl_xor_sync(0xffffffffu, ss, o);
        float rv = rsqrtf(ss * (1.f / DMX) + EPSF);
        acc.x += v.x * rv; acc.y += v.y * rv;
        acc.z += v.z * rv; acc.w += v.w * rv;
    }
    float inv = 1.f / TT;
    acc.x *= inv * wnf.x; acc.y *= inv * wnf.y;
    acc.z *= inv * wnf.z; acc.w *= inv * wnf.w;
    *(float4*)(g_POOLP + (size_t)(b * 32 + chunk * 8 + wid) * DMX + lane * 4) = acc;
}

__global__ void final_kernel(const float* __restrict__ ow,
                             const float* __restrict__ ob,
                             float* __restrict__ out)
{
    int b = blockIdx.x;
    int j = threadIdx.x;
    __shared__ float p[DMX];
    if (j < DMX) {
        float s = 0.f;
#pragma unroll 8
        for (int k = 0; k < 32; k++) s += g_POOLP[(size_t)(b * 32 + k) * DMX + j];
        p[j] = s;
    }
    __syncthreads();
    float acc = ob[j];
#pragma unroll 4
    for (int k = 0; k < DMX; k++) acc += p[k] * ow[k * DIMX + j];
    out[b * DIMX + j] = acc;
}

// ------------------------------ launcher -------------------------------------
extern "C" void kernel_launch(void* const* d_in, const int* in_sizes, int n_in,
                              void* d_out, int out_size)
{
    const float* x         = (const float*)d_in[0];
    const float* in_w      = (const float*)d_in[1];
    const float* in_b      = (const float*)d_in[2];
    const float* norm_w    = (const float*)d_in[3];
    const float* inproj_w  = (const float*)d_in[4];
    const float* conv_w    = (const float*)d_in[5];
    const float* conv_b    = (const float*)d_in[6];
    const float* A_log     = (const float*)d_in[7];
    const float* Dparam    = (const float*)d_in[8];
    const float* dt_bias   = (const float*)d_in[9];
    const float* gnorm_w   = (const float*)d_in[10];
    const float* outproj_w = (const float*)d_in[11];
    const float* normf_w   = (const float*)d_in[12];
    const float* out_w     = (const float*)d_in[13];
    const float* out_b     = (const float*)d_in[14];

    float *pH, *pPROJ;
    __half *pXh, *pHNh, *pYNh, *pW1, *pW2, *pW3;
    cudaGetSymbolAddress((void**)&pH,    g_H);
    cudaGetSymbolAddress((void**)&pPROJ, g_PROJ);
    cudaGetSymbolAddress((void**)&pXh,   g_xh);
    cudaGetSymbolAddress((void**)&pHNh,  g_hnh);
    cudaGetSymbolAddress((void**)&pYNh,  g_ynh);
    cudaGetSymbolAddress((void**)&pW1,   g_w1h);
    cudaGetSymbolAddress((void**)&pW2,   g_w2h);
    cudaGetSymbolAddress((void**)&pW3,   g_w3h);

    cudaFuncSetAttribute(mma_gemm<0>, cudaFuncAttributeMaxDynamicSharedMemorySize, SM_TOTAL);
    cudaFuncSetAttribute(mma_gemm<1>, cudaFuncAttributeMaxDynamicSharedMemorySize, SM_TOTAL);
    cudaFuncSetAttribute(mma_gemm<2>, cudaFuncAttributeMaxDynamicSharedMemorySize, SM_TOTAL);
    cudaFuncSetAttribute(ssd_mma_kernel, cudaFuncAttributeMaxDynamicSharedMemorySize, SSD_SMEM);

    prep_kernel<<<(PREP_N + 255) / 256, 256>>>(x, in_w, inproj_w, outproj_w);

    // h = x @ in_w + in_b
    mma_gemm<0><<<dim3(DMX / 64, BT / 128), 256, SM_TOTAL>>>(
        pXh, pW1, in_b, pH, DMX, DIMX);

    for (int l = 0; l < LNUM; l++) {
        rmsnorm128_kernel<<<BT / 8, 256>>>(pH, norm_w + l * DMX, pHNh);
        mma_gemm<1><<<dim3(PROJPAD / 64, BT / 128), 256, SM_TOTAL>>>(
            pHNh, pW2 + (size_t)l * PROJPAD * DMX, nullptr, pPROJ, PROJD, DMX);
        conv_kernel<<<dim3(TT / 32, BB), 288>>>(
            conv_w + l * CONVD * 4, conv_b + l * CONVD);
        chunkstate_kernel<<<dim3(NCHK, BHX), 256>>>(A_log + l * NHX, dt_bias + l * NHX);
        ssd_mma_kernel<<<dim3(NCHK, BHX), 256, SSD_SMEM>>>(Dparam + l * NHX);
        gatednorm_kernel<<<BT / 8, 256>>>(gnorm_w + l * DINNERX);
        mma_gemm<2><<<dim3(DMX / 64, BT / 128), 256, SM_TOTAL>>>(
            pYNh, pW3 + (size_t)l * DMX * DINNERX, nullptr, pH, DMX, DINNERX);
    }

    pool_kernel<<<dim3(4, BB), 256>>>(normf_w);
    final_kernel<<<BB, DIMX>>>(out_w, out_b, (float*)d_out);
}

// round 17
// speedup vs baseline: 1.1270x; 1.0168x over previous
#include <cuda_runtime.h>
#include <cuda_fp16.h>
#include <math.h>
#include <stdint.h>

#define BB 8
#define TT 2048
#define DIMX 512
#define DMX 128
#define DINNERX 256
#define NSTATEX 16
#define HDIMX 64
#define NHX 4
#define CONVD 288
#define PROJD 548
#define PROJPAD 576
#define LNUM 2
#define BT (BB*TT)          // 16384
#define QC 128
#define NCHK (TT/QC)        // 16
#define BHX (BB*NHX)        // 32
#define EPSF 1e-5f

// ------------------------- scratch (static device memory) -------------------
__device__ float g_H[BT*DMX];
__device__ float g_PROJ[BT*PROJD];
__device__ __half g_CONVX[BT*CONVD];
__device__ float g_DT[BHX*TT];
__device__ float g_CUM[BHX*TT];
__device__ float g_SLOC[BHX*NCHK*HDIMX*NSTATEX];
__device__ __half g_Y[BT*DINNERX];
__device__ float g_POOLP[BB*32*DMX];

__device__ __half g_xh[BT*DIMX];
__device__ __half g_hnh[BT*DMX];
__device__ __half g_ynh[BT*DINNERX];
__device__ __half g_w1h[DMX*DIMX];                 // in_w^T [128][512]
__device__ __half g_w2h[LNUM*PROJPAD*DMX];         // inproj^T [576][128]
__device__ __half g_w3h[LNUM*DMX*DINNERX];         // outproj^T [128][256]

// ------------------------------ PTX helpers ---------------------------------
__device__ __forceinline__ uint32_t smem_u32(const void* p) {
    uint32_t a;
    asm("{ .reg .u64 t; cvta.to.shared.u64 t, %1; cvt.u32.u64 %0, t; }" : "=r"(a) : "l"(p));
    return a;
}
__device__ __forceinline__ void ldsm_x4(uint32_t* r, uint32_t addr) {
    asm volatile("ldmatrix.sync.aligned.m8n8.x4.shared.b16 {%0,%1,%2,%3}, [%4];"
        : "=r"(r[0]), "=r"(r[1]), "=r"(r[2]), "=r"(r[3]) : "r"(addr));
}
__device__ __forceinline__ void mma16816(float* c, const uint32_t* a, const uint32_t* b) {
    asm volatile("mma.sync.aligned.m16n8k16.row.col.f32.f16.f16.f32 "
        "{%0,%1,%2,%3}, {%4,%5,%6,%7}, {%8,%9}, {%0,%1,%2,%3};"
        : "+f"(c[0]), "+f"(c[1]), "+f"(c[2]), "+f"(c[3])
        : "r"(a[0]), "r"(a[1]), "r"(a[2]), "r"(a[3]), "r"(b[0]), "r"(b[1]));
}
__device__ __forceinline__ void cp16(uint32_t saddr, const void* g) {
    asm volatile("cp.async.ca.shared.global [%0], [%1], 16;" :: "r"(saddr), "l"(g));
}
__device__ __forceinline__ void cp_commit() {
    asm volatile("cp.async.commit_group;" ::: "memory");
}
template<int N> __device__ __forceinline__ void cp_wait() {
    asm volatile("cp.async.wait_group %0;" :: "n"(N) : "memory");
}

// ------------------------------ HMMA GEMM (1-term fp16) ----------------------
#define LDSA 72
#define A_BYTES (128*LDSA*2)                 // 18432
#define B_BYTES (64*LDSA*2)                  // 9216
#define OFF_B A_BYTES
#define STAGE_BYTES (A_BYTES + B_BYTES)      // 27648
#define SM_TOTAL (2*STAGE_BYTES)             // 55296

template<int MODE>   // 0: C=D+bias ; 1: C=D ; 2: C+=D
__global__ __launch_bounds__(256, 2) void mma_gemm(
    const __half* __restrict__ A, const __half* __restrict__ Wt,
    const float* __restrict__ bias, float* __restrict__ C,
    int N, int K)
{
    extern __shared__ char smem[];
    uint32_t sb = smem_u32(smem);
    int tid = threadIdx.x, wid = tid >> 5, lane = tid & 31;
    int m0 = blockIdx.y * 128, n0 = blockIdx.x * 64;
    int wm = (wid & 3) * 32, wn = (wid >> 2) * 32;

    float acc[2][4][4];
#pragma unroll
    for (int i = 0; i < 2; i++)
#pragma unroll
        for (int j = 0; j < 4; j++)
#pragma unroll
            for (int q = 0; q < 4; q++) acc[i][j][q] = 0.f;

    int lr = lane & 15;
    uint32_t aOff[2];
#pragma unroll
    for (int mt = 0; mt < 2; mt++)
        aOff[mt] = (uint32_t)((wm + mt * 16 + lr) * (LDSA * 2) + (lane >> 4) * 16);
    uint32_t bOff[2];
    {
        int q = lane >> 3, rr = lane & 7;
#pragma unroll
        for (int p = 0; p < 2; p++) {
            int row = wn + p * 16 + (q >> 1) * 8 + rr;
            bOff[p] = (uint32_t)(OFF_B + row * (LDSA * 2) + (q & 1) * 16);
        }
    }

    int nstage = K >> 6;
    auto load_stage = [&](int buf, int k0) {
        uint32_t base = sb + buf * STAGE_BYTES;
#pragma unroll
        for (int i = 0; i < 4; i++) {
            int li = tid + i * 256;
            int r = li >> 3, g8 = li & 7;
            uint32_t so = (uint32_t)(r * (LDSA * 2) + g8 * 16);
            cp16(base + so, A + (size_t)(m0 + r) * K + k0 + g8 * 8);
        }
#pragma unroll
        for (int i = 0; i < 2; i++) {
            int li = tid + i * 256;
            int r = li >> 3, g8 = li & 7;
            uint32_t so = (uint32_t)(r * (LDSA * 2) + g8 * 16);
            cp16(base + OFF_B + so, Wt + (size_t)(n0 + r) * K + k0 + g8 * 8);
        }
    };

    load_stage(0, 0);
    cp_commit();

    for (int s = 0; s < nstage; s++) {
        if (s + 1 < nstage) load_stage((s + 1) & 1, (s + 1) * 64);
        cp_commit();
        if (s + 1 < nstage) cp_wait<1>(); else cp_wait<0>();
        __syncthreads();

        uint32_t sbuf = sb + (s & 1) * STAGE_BYTES;
#pragma unroll
        for (int ks = 0; ks < 64; ks += 16) {
            uint32_t kb = (uint32_t)(ks * 2);
            uint32_t ah[2][4], b4[2][4];
#pragma unroll
            for (int mt = 0; mt < 2; mt++)
                ldsm_x4(ah[mt], sbuf + aOff[mt] + kb);
#pragma unroll
            for (int p = 0; p < 2; p++)
                ldsm_x4(b4[p], sbuf + bOff[p] + kb);
#pragma unroll
            for (int mt = 0; mt < 2; mt++)
#pragma unroll
                for (int p = 0; p < 2; p++)
#pragma unroll
                    for (int u = 0; u < 2; u++)
                        mma16816(acc[mt][2 * p + u], ah[mt], &b4[p][u * 2]);
        }
        __syncthreads();
    }

    float* S = (float*)smem;          // [128][68]
    const int SW = 68;
    int crow = lane >> 2, ccol = (lane & 3) * 2;
#pragma unroll
    for (int mt = 0; mt < 2; mt++)
#pragma unroll
        for (int nt = 0; nt < 4; nt++) {
            int r = wm + mt * 16 + crow;
            int cc = wn + nt * 8 + ccol;
            S[r * SW + cc]           = acc[mt][nt][0];
            S[r * SW + cc + 1]       = acc[mt][nt][1];
            S[(r + 8) * SW + cc]     = acc[mt][nt][2];
            S[(r + 8) * SW + cc + 1] = acc[mt][nt][3];
        }
    __syncthreads();
#pragma unroll
    for (int it = 0; it < 32; it++) {
        int li = tid + it * 256;
        int cc = li & 63, r = li >> 6;
        int col = n0 + cc;
        if (col < N) {
            float v = S[r * SW + cc];
            if (MODE == 0) v += bias[col];
            size_t o = (size_t)(m0 + r) * N + col;
            if (MODE == 2) v += C[o];
            C[o] = v;
        }
    }
}

// --------------------------- fused prep (x split + weight transposes) --------
#define XN4 (BT*DIMX/4)
#define TS_R1 (DMX*DIMX)
#define TS_R2 (LNUM*PROJPAD*DMX)
#define TS_R3 (LNUM*DMX*DINNERX)
#define PREP_N (XN4 + TS_R1 + TS_R2 + TS_R3)
__global__ void prep_kernel(const float* __restrict__ x,
                            const float* __restrict__ in_w,
                            const float* __restrict__ inproj_w,
                            const float* __restrict__ outproj_w)
{
    int idx = blockIdx.x * blockDim.x + threadIdx.x;
    if (idx < XN4) {
        float4 v = ((const float4*)x)[idx];
        __half h[4] = { __float2half_rn(v.x), __float2half_rn(v.y),
                        __float2half_rn(v.z), __float2half_rn(v.w) };
        *(uint2*)(g_xh + (size_t)idx * 4) = *(uint2*)h;
        return;
    }
    idx -= XN4;
    if (idx < TS_R1) {
        int n = idx / DIMX, k = idx % DIMX;
        g_w1h[idx] = __float2half_rn(in_w[(size_t)k * DMX + n]);
        return;
    }
    idx -= TS_R1;
    if (idx < TS_R2) {
        int l = idx / (PROJPAD * DMX), r = idx % (PROJPAD * DMX);
        int n = r / DMX, k = r % DMX;
        float v = (n < PROJD) ? inproj_w[(size_t)l * DMX * PROJD + (size_t)k * PROJD + n] : 0.f;
        g_w2h[idx] = __float2half_rn(v);
        return;
    }
    idx -= TS_R2;
    if (idx < TS_R3) {
        int l = idx / (DMX * DINNERX), r = idx % (DMX * DINNERX);
        int n = r / DINNERX, k = r % DINNERX;
        g_w3h[idx] = __float2half_rn(outproj_w[(size_t)l * DINNERX * DMX + (size_t)k * DMX + n]);
    }
}

// ------------------------------ rmsnorm (DM=128) -----------------------------
__global__ void rmsnorm128_kernel(const float* __restrict__ src,
                                  const float* __restrict__ w,
                                  __half* __restrict__ dst)
{
    int warp = (blockIdx.x * blockDim.x + threadIdx.x) >> 5;
    int lane = threadIdx.x & 31;
    if (warp >= BT) return;
    const float* row = src + (size_t)warp * DMX;
    float4 v = *(const float4*)(row + lane * 4);
    float ss = v.x*v.x + v.y*v.y + v.z*v.z + v.w*v.w;
#pragma unroll
    for (int o = 16; o; o >>= 1) ss += __shfl_xor_sync(0xffffffffu, ss, o);
    float r = rsqrtf(ss * (1.f / DMX) + EPSF);
    float4 wv = *(const float4*)(w + lane * 4);
    __half h[4] = { __float2half_rn(v.x*r*wv.x), __float2half_rn(v.y*r*wv.y),
                    __float2half_rn(v.z*r*wv.z), __float2half_rn(v.w*r*wv.w) };
    *(uint2*)(dst + (size_t)warp * DMX + lane * 4) = *(uint2*)h;
}

// ------------------------ causal conv + silu (32 t/block) --------------------
__global__ __launch_bounds__(288) void conv_kernel(const float* __restrict__ cw,
                                                   const float* __restrict__ cb)
{
    int b = blockIdx.y;
    int t0 = blockIdx.x * 32;
    int c = threadIdx.x;
    float w0 = cw[c*4], w1 = cw[c*4+1], w2 = cw[c*4+2], w3 = cw[c*4+3];
    float bias = cb[c];
    size_t base = (size_t)(b * TT) * PROJD + DINNERX + c;
    float xm3 = 0.f, xm2 = 0.f, xm1 = 0.f;
    if (t0 >= 3) {
        xm3 = g_PROJ[base + (size_t)(t0-3) * PROJD];
        xm2 = g_PROJ[base + (size_t)(t0-2) * PROJD];
        xm1 = g_PROJ[base + (size_t)(t0-1) * PROJD];
    }
    for (int i = 0; i < 4; i++) {
        float xv[8];
#pragma unroll
        for (int j = 0; j < 8; j++)
            xv[j] = g_PROJ[base + (size_t)(t0 + i*8 + j) * PROJD];
#pragma unroll
        for (int j = 0; j < 8; j++) {
            float a = bias + w0*xm3 + w1*xm2 + w2*xm1 + w3*xv[j];
            g_CONVX[(size_t)(b * TT + t0 + i*8 + j) * CONVD + c] =
                __float2half_rn(a / (1.f + __expf(-a)));
            xm3 = xm2; xm2 = xm1; xm1 = xv[j];
        }
    }
}

// ---------------- chunkstate: full-tile load, single sync --------------------
__global__ __launch_bounds__(256) void chunkstate_kernel(const float* __restrict__ Alog,
                                                         const float* __restrict__ dtb)
{
    int c = blockIdx.x, bh = blockIdx.y;
    int b = bh >> 2, h = bh & 3;
    int tid = threadIdx.x;
    __shared__ float sc[QC];
    __shared__ float sdt[QC];
    __shared__ float coef[QC];
    __shared__ float Xs[QC][HDIMX];      // 32 KB
    __shared__ float Bsh[QC][NSTATEX];   //  8 KB
    int cbase = bh * TT + c * QC;
    size_t rowbase = (size_t)(b * TT + c * QC);

    float Ah = -__expf(Alog[h]);
    if (tid < QC) {
        float v = g_PROJ[(rowbase + tid) * PROJD + DINNERX + CONVD + h] + dtb[h];
        float sp = (v > 20.f) ? v : log1pf(__expf(v));
        sdt[tid] = sp;
        sc[tid] = sp * Ah;
    }
    // full X tile: 128 rows x 64 halves = 1024 uint4 chunks
#pragma unroll
    for (int i = 0; i < 4; i++) {
        int li = tid + i * 256;
        int r = li >> 3, g8 = li & 7;
        __half hx[8];
        *(uint4*)hx = *(const uint4*)(g_CONVX + (rowbase + r) * CONVD + h * 64 + g8 * 8);
#pragma unroll
        for (int k = 0; k < 8; k++) Xs[r][g8 * 8 + k] = __half2float(hx[k]);
    }
    // full B tile: 128 rows x 16 halves = 256 uint4 chunks
    {
        int r = tid >> 1, g8 = tid & 1;
        __half hb[8];
        *(uint4*)hb = *(const uint4*)(g_CONVX + (rowbase + r) * CONVD + 256 + g8 * 8);
#pragma unroll
        for (int k = 0; k < 8; k++) Bsh[r][g8 * 8 + k] = __half2float(hb[k]);
    }
    __syncthreads();
#pragma unroll
    for (int off = 1; off < QC; off <<= 1) {
        float x = 0.f;
        if (tid < QC && tid >= off) x = sc[tid - off];
        __syncthreads();
        if (tid < QC) sc[tid] += x;
        __syncthreads();
    }
    if (tid < QC) {
        g_DT[cbase + tid]  = sdt[tid];
        g_CUM[cbase + tid] = sc[tid];
        coef[tid] = __expf(sc[QC - 1] - sc[tid]) * sdt[tid];
    }
    __syncthreads();

    float acc[4] = {0.f, 0.f, 0.f, 0.f};
    int p = tid >> 2, ng = (tid & 3) * 4;
#pragma unroll 4
    for (int r = 0; r < QC; r++) {
        float cx = coef[r] * Xs[r][p];
        float4 bv = *(const float4*)&Bsh[r][ng];
        acc[0] += cx * bv.x; acc[1] += cx * bv.y;
        acc[2] += cx * bv.z; acc[3] += cx * bv.w;
    }
    size_t dst = ((size_t)bh * NCHK + c) * (HDIMX * NSTATEX) + p * NSTATEX + ng;
    *(float4*)(g_SLOC + dst) = make_float4(acc[0], acc[1], acc[2], acc[3]);
}

// ============================ SSD via HMMA ===================================
#define SCB_STR 24
#define XT_STR 152
#define OFF_SC 0
#define OFF_SB 6144
#define OFF_XT 12288
#define OFF_G  31744
#define OFF_CUM 70656
#define OFF_SDT 71168
#define SSD_SMEM 71680

__global__ __launch_bounds__(256, 2) void ssd_mma_kernel(const float* __restrict__ Dp)
{
    extern __shared__ char sm[];
    __half* sC  = (__half*)(sm + OFF_SC);
    __half* sB  = (__half*)(sm + OFF_SB);
    __half* sXT = (__half*)(sm + OFF_XT);
    __half* sG  = (__half*)(sm + OFF_G);
    float*  sCum = (float*)(sm + OFF_CUM);
    float*  sDt  = (float*)(sm + OFF_SDT);
    float*  sYf  = (float*)(sm + OFF_G);
    uint32_t sb = smem_u32(sm);

    int c = blockIdx.x, bh = blockIdx.y;
    int b = bh >> 2, h = bh & 3;
    int tid = threadIdx.x, wid = tid >> 5, lane = tid & 31;
    size_t rowbase = (size_t)(b * TT + c * QC);
    int cbase = bh * TT + c * QC;

    if (tid < QC) { sCum[tid] = g_CUM[cbase + tid]; sDt[tid] = g_DT[cbase + tid]; }
#pragma unroll
    for (int jj = 0; jj < 8; jj++) {
        int e = tid + jj * 256;
        int r = e >> 4, n = e & 15;
        sC[r * SCB_STR + n] = g_CONVX[(rowbase + r) * CONVD + 272 + n];
        sB[r * SCB_STR + n] = g_CONVX[(rowbase + r) * CONVD + 256 + n];
    }
#pragma unroll
    for (int jj = 0; jj < 32; jj++) {
        int e = tid + jj * 256;
        int s = e >> 6, p = e & 63;
        sXT[p * XT_STR + s] = g_CONVX[(rowbase + s) * CONVD + h * 64 + p];
    }
    // prefix over earlier chunks — software-pipelined (MLP 8)
    {
        size_t sbase = (size_t)bh * NCHK * (HDIMX * NSTATEX);
        int i = tid * 4;
        float4 s4 = make_float4(0.f, 0.f, 0.f, 0.f);
        int j = 0;
        while (j < c) {
            int m = c - j; if (m > 4) m = 4;
            float pd[4]; float4 pa[4];
#pragma unroll
            for (int u = 0; u < 4; u++) {
                if (u < m) {
                    pd[u] = g_CUM[bh * TT + (j + u) * QC + QC - 1];
                    pa[u] = *(const float4*)(g_SLOC + sbase + (size_t)(j + u) * (HDIMX * NSTATEX) + i);
                }
            }
#pragma unroll
            for (int u = 0; u < 4; u++) {
                if (u < m) {
                    float dj = __expf(pd[u]);
                    s4.x = s4.x * dj + pa[u].x; s4.y = s4.y * dj + pa[u].y;
                    s4.z = s4.z * dj + pa[u].z; s4.w = s4.w * dj + pa[u].w;
                }
            }
            j += m;
        }
        int p = i >> 4, n0 = i & 15;
        __half hv[4] = { __float2half_rn(s4.x), __float2half_rn(s4.y),
                         __float2half_rn(s4.z), __float2half_rn(s4.w) };
        *(uint2*)(sXT + p * XT_STR + 128 + n0) = *(uint2*)hv;
    }
    __syncthreads();

    // phase A: S = C @ B^T
    int wm = (wid & 3) * 32, wn = (wid >> 2) * 64;
    float sacc[2][8][4];
#pragma unroll
    for (int i = 0; i < 2; i++)
#pragma unroll
        for (int j = 0; j < 8; j++)
#pragma unroll
            for (int q = 0; q < 4; q++) sacc[i][j][q] = 0.f;
    {
        uint32_t aC[2][4], bB[4][4];
        int lr = lane & 15;
#pragma unroll
        for (int mt = 0; mt < 2; mt++)
            ldsm_x4(aC[mt], sb + OFF_SC + (uint32_t)((wm + mt * 16 + lr) * (SCB_STR * 2) + (lane >> 4) * 16));
        int q = lane >> 3, rr = lane & 7;
#pragma unroll
        for (int p4 = 0; p4 < 4; p4++) {
            int row = wn + p4 * 16 + (q >> 1) * 8 + rr;
            ldsm_x4(bB[p4], sb + OFF_SB + (uint32_t)(row * (SCB_STR * 2) + (q & 1) * 16));
        }
#pragma unroll
        for (int mt = 0; mt < 2; mt++)
#pragma unroll
            for (int p4 = 0; p4 < 4; p4++)
#pragma unroll
                for (int u = 0; u < 2; u++)
                    mma16816(sacc[mt][p4 * 2 + u], aC[mt], &bB[p4][u * 2]);
    }

    // weighting -> G fp16
    int crow = lane >> 2, ccol = (lane & 3) * 2;
#pragma unroll
    for (int mt = 0; mt < 2; mt++) {
        int t0 = wm + mt * 16 + crow, t1 = t0 + 8;
        float ct0 = sCum[t0], ct1 = sCum[t1];
#pragma unroll
        for (int nt = 0; nt < 8; nt++) {
            int s0 = wn + nt * 8 + ccol, s1 = s0 + 1;
            float cs0 = sCum[s0], cs1 = sCum[s1];
            float d0 = sDt[s0], d1 = sDt[s1];
            float v0 = (s0 <= t0) ? __expf(ct0 - cs0) * d0 * sacc[mt][nt][0] : 0.f;
            float v1 = (s1 <= t0) ? __expf(ct0 - cs1) * d1 * sacc[mt][nt][1] : 0.f;
            float v2 = (s0 <= t1) ? __expf(ct1 - cs0) * d0 * sacc[mt][nt][2] : 0.f;
            float v3 = (s1 <= t1) ? __expf(ct1 - cs1) * d1 * sacc[mt][nt][3] : 0.f;
            *(__half2*)(sG + t0 * XT_STR + s0) = __floats2half2_rn(v0, v1);
            *(__half2*)(sG + t1 * XT_STR + s0) = __floats2half2_rn(v2, v3);
        }
    }
#pragma unroll
    for (int jj = 0; jj < 8; jj++) {
        int e = tid + jj * 256;
        int t = e >> 4, n = e & 15;
        sG[t * XT_STR + 128 + n] =
            __float2half_rn(__expf(sCum[t]) * __half2float(sC[t * SCB_STR + n]));
    }
    __syncthreads();

    // phase B: Y = G @ X'
    int wm2 = (wid & 3) * 32, wn2 = (wid >> 2) * 32;
    float acc2[2][4][4];
#pragma unroll
    for (int i = 0; i < 2; i++)
#pragma unroll
        for (int j = 0; j < 4; j++)
#pragma unroll
            for (int q = 0; q < 4; q++) acc2[i][j][q] = 0.f;
    {
        int lr = lane & 15;
        int q = lane >> 3, rr = lane & 7;
        uint32_t aOff2[2], bOff2[2];
#pragma unroll
        for (int mt = 0; mt < 2; mt++)
            aOff2[mt] = sb + OFF_G + (uint32_t)((wm2 + mt * 16 + lr) * (XT_STR * 2) + (lane >> 4) * 16);
#pragma unroll
        for (int pp = 0; pp < 2; pp++) {
            int row = wn2 + pp * 16 + (q >> 1) * 8 + rr;
            bOff2[pp] = sb + OFF_XT + (uint32_t)(row * (XT_STR * 2) + (q & 1) * 16);
        }
#pragma unroll
        for (int k9 = 0; k9 < 9; k9++) {
            uint32_t kb = (uint32_t)(k9 * 32);
            uint32_t aG[2][4], bX[2][4];
#pragma unroll
            for (int mt = 0; mt < 2; mt++)
                ldsm_x4(aG[mt], aOff2[mt] + kb);
#pragma unroll
            for (int pp = 0; pp < 2; pp++)
                ldsm_x4(bX[pp], bOff2[pp] + kb);
#pragma unroll
            for (int mt = 0; mt < 2; mt++)
#pragma unroll
                for (int pp = 0; pp < 2; pp++)
#pragma unroll
                    for (int u = 0; u < 2; u++)
                        mma16816(acc2[mt][pp * 2 + u], aG[mt], &bX[pp][u * 2]);
        }
    }
    __syncthreads();

    float Dh = Dp[h];
#pragma unroll
    for (int mt = 0; mt < 2; mt++)
#pragma unroll
        for (int nt = 0; nt < 4; nt++) {
            int t0 = wm2 + mt * 16 + crow, t1 = t0 + 8;
            int p0 = wn2 + nt * 8 + ccol, p1 = p0 + 1;
            sYf[t0 * 68 + p0] = acc2[mt][nt][0] + Dh * __half2float(sXT[p0 * XT_STR + t0]);
            sYf[t0 * 68 + p1] = acc2[mt][nt][1] + Dh * __half2float(sXT[p1 * XT_STR + t0]);
            sYf[t1 * 68 + p0] = acc2[mt][nt][2] + Dh * __half2float(sXT[p0 * XT_STR + t1]);
            sYf[t1 * 68 + p1] = acc2[mt][nt][3] + Dh * __half2float(sXT[p1 * XT_STR + t1]);
        }
    __syncthreads();
#pragma unroll
    for (int jj = 0; jj < 32; jj++) {
        int e = tid + jj * 256;
        int r = e >> 6, p = e & 63;
        g_Y[(rowbase + r) * DINNERX + h * 64 + p] = __float2half_rn(sYf[r * 68 + p]);
    }
}

// --------------------------- gated rmsnorm (fp16 Y) --------------------------
__global__ void gatednorm_kernel(const float* __restrict__ gnw)
{
    int warp = (blockIdx.x * blockDim.x + threadIdx.x) >> 5;
    int lane = threadIdx.x & 31;
    if (warp >= BT) return;
    const __half* yr = g_Y + (size_t)warp * DINNERX;
    const float4* gr = (const float4*)(g_PROJ + (size_t)warp * PROJD);
    __half yh[8];
    *(uint4*)yh = *(const uint4*)(yr + lane * 8);
    float v[8];
    float ss = 0.f;
#pragma unroll
    for (int q = 0; q < 2; q++) {
        float4 gv = gr[lane * 2 + q];
        float gy[4] = { gv.x, gv.y, gv.z, gv.w };
#pragma unroll
        for (int i = 0; i < 4; i++) {
            float s = gy[i] / (1.f + __expf(-gy[i]));
            float t = __half2float(yh[q * 4 + i]) * s;
            v[q * 4 + i] = t;
            ss += t * t;
        }
    }
#pragma unroll
    for (int o = 16; o; o >>= 1) ss += __shfl_xor_sync(0xffffffffu, ss, o);
    float r = rsqrtf(ss * (1.f / DINNERX) + EPSF);
    size_t base = (size_t)warp * DINNERX + lane * 8;
    __half h[8];
#pragma unroll
    for (int i = 0; i < 8; i++) h[i] = __float2half_rn(v[i] * r * gnw[lane * 8 + i]);
    *(uint4*)(g_ynh + base) = *(uint4*)h;
}

// ---------------------------- final pool + head ------------------------------
__global__ __launch_bounds__(256) void pool_kernel(const float* __restrict__ nfw)
{
    int b = blockIdx.y;
    int chunk = blockIdx.x;            // 0..3
    int wid = threadIdx.x >> 5, lane = threadIdx.x & 31;
    float4 wnf = *(const float4*)(nfw + lane * 4);
    float4 acc = make_float4(0.f, 0.f, 0.f, 0.f);
    int t0 = chunk * 512 + wid * 64;
    for (int r = 0; r < 64; r++) {
        int t = t0 + r;
        float4 v = *(const float4*)(g_H + (size_t)(b * TT + t) * DMX + lane * 4);
        float ss = v.x*v.x + v.y*v.y + v.z*v.z + v.w*v.w;
#pragma unroll
        for (int o = 16; o; o >>= 1) ss += __shfl_xor_sync(0xffffffffu, ss, o);
        float rv = rsqrtf(ss * (1.f / DMX) + EPSF);
        acc.x += v.x * rv; acc.y += v.y * rv;
        acc.z += v.z * rv; acc.w += v.w * rv;
    }
    float inv = 1.f / TT;
    acc.x *= inv * wnf.x; acc.y *= inv * wnf.y;
    acc.z *= inv * wnf.z; acc.w *= inv * wnf.w;
    *(float4*)(g_POOLP + (size_t)(b * 32 + chunk * 8 + wid) * DMX + lane * 4) = acc;
}

__global__ void final_kernel(const float* __restrict__ ow,
                             const float* __restrict__ ob,
                             float* __restrict__ out)
{
    int b = blockIdx.x;
    int j = threadIdx.x;
    __shared__ float p[DMX];
    if (j < DMX) {
        float s = 0.f;
#pragma unroll 8
        for (int k = 0; k < 32; k++) s += g_POOLP[(size_t)(b * 32 + k) * DMX + j];
        p[j] = s;
    }
    __syncthreads();
    float acc = ob[j];
#pragma unroll 4
    for (int k = 0; k < DMX; k++) acc += p[k] * ow[k * DIMX + j];
    out[b * DIMX + j] = acc;
}

// ------------------------------ launcher -------------------------------------
extern "C" void kernel_launch(void* const* d_in, const int* in_sizes, int n_in,
                              void* d_out, int out_size)
{
    const float* x         = (const float*)d_in[0];
    const float* in_w      = (const float*)d_in[1];
    const float* in_b      = (const float*)d_in[2];
    const float* norm_w    = (const float*)d_in[3];
    const float* inproj_w  = (const float*)d_in[4];
    const float* conv_w    = (const float*)d_in[5];
    const float* conv_b    = (const float*)d_in[6];
    const float* A_log     = (const float*)d_in[7];
    const float* Dparam    = (const float*)d_in[8];
    const float* dt_bias   = (const float*)d_in[9];
    const float* gnorm_w   = (const float*)d_in[10];
    const float* outproj_w = (const float*)d_in[11];
    const float* normf_w   = (const float*)d_in[12];
    const float* out_w     = (const float*)d_in[13];
    const float* out_b     = (const float*)d_in[14];

    float *pH, *pPROJ;
    __half *pXh, *pHNh, *pYNh, *pW1, *pW2, *pW3;
    cudaGetSymbolAddress((void**)&pH,    g_H);
    cudaGetSymbolAddress((void**)&pPROJ, g_PROJ);
    cudaGetSymbolAddress((void**)&pXh,   g_xh);
    cudaGetSymbolAddress((void**)&pHNh,  g_hnh);
    cudaGetSymbolAddress((void**)&pYNh,  g_ynh);
    cudaGetSymbolAddress((void**)&pW1,   g_w1h);
    cudaGetSymbolAddress((void**)&pW2,   g_w2h);
    cudaGetSymbolAddress((void**)&pW3,   g_w3h);

    cudaFuncSetAttribute(mma_gemm<0>, cudaFuncAttributeMaxDynamicSharedMemorySize, SM_TOTAL);
    cudaFuncSetAttribute(mma_gemm<1>, cudaFuncAttributeMaxDynamicSharedMemorySize, SM_TOTAL);
    cudaFuncSetAttribute(mma_gemm<2>, cudaFuncAttributeMaxDynamicSharedMemorySize, SM_TOTAL);
    cudaFuncSetAttribute(ssd_mma_kernel, cudaFuncAttributeMaxDynamicSharedMemorySize, SSD_SMEM);

    prep_kernel<<<(PREP_N + 255) / 256, 256>>>(x, in_w, inproj_w, outproj_w);

    // h = x @ in_w + in_b
    mma_gemm<0><<<dim3(DMX / 64, BT / 128), 256, SM_TOTAL>>>(
        pXh, pW1, in_b, pH, DMX, DIMX);

    for (int l = 0; l < LNUM; l++) {
        rmsnorm128_kernel<<<BT / 8, 256>>>(pH, norm_w + l * DMX, pHNh);
        mma_gemm<1><<<dim3(PROJPAD / 64, BT / 128), 256, SM_TOTAL>>>(
            pHNh, pW2 + (size_t)l * PROJPAD * DMX, nullptr, pPROJ, PROJD, DMX);
        conv_kernel<<<dim3(TT / 32, BB), 288>>>(
            conv_w + l * CONVD * 4, conv_b + l * CONVD);
        chunkstate_kernel<<<dim3(NCHK, BHX), 256>>>(A_log + l * NHX, dt_bias + l * NHX);
        ssd_mma_kernel<<<dim3(NCHK, BHX), 256, SSD_SMEM>>>(Dparam + l * NHX);
        gatednorm_kernel<<<BT / 8, 256>>>(gnorm_w + l * DINNERX);
        mma_gemm<2><<<dim3(DMX / 64, BT / 128), 256, SM_TOTAL>>>(
            pYNh, pW3 + (size_t)l * DMX * DINNERX, nullptr, pH, DMX, DINNERX);
    }

    pool_kernel<<<dim3(4, BB), 256>>>(normf_w);
    final_kernel<<<BB, DIMX>>>(out_w, out_b, (float*)d_out);
}